// round 1
// baseline (speedup 1.0000x reference)
#include <cuda_runtime.h>
#include <math.h>

#define BB 16
#define NN 1024
#define KK 16
#define MSGD 128
#define PI_F 3.14159265358979323846f
#define TWOPI_F 6.28318530717958647692f
#define EPS_F 1e-8f

// ---------------- device scratch (no allocations allowed) ----------------
__device__ int   g_maskmode;
__device__ __align__(16) float g_lvpack[BB*NN*8];   // px,py,pz,e,pt,rap,phi,mask
__device__ int   g_idx[BB*NN*KK];
__device__ __align__(16) float g_u[BB*NN*MSGD];     // (b,n,o) contiguous in o
__device__ __align__(16) float g_v[BB*NN*MSGD];
__device__ __align__(16) float g_cnt[BB*NN];
__device__ float g_S[BB*MSGD];
__device__ float g_nb[BB];
__device__ float g_y[BB*MSGD];

// ---------------- k0: detect mask dtype ----------------
__global__ void k0_detect(const unsigned int* mw) {
    if (threadIdx.x == 0) {
        int allf = 1, alli = 1;
        for (int q = 0; q < 64; q++) {
            unsigned int w = mw[q];
            if (!(w == 0u || w == 0x3F800000u)) allf = 0;
            if (!(w == 0u || w == 1u))          alli = 0;
        }
        g_maskmode = allf ? 0 : (alli ? 1 : 2);
    }
}

// ---------------- k1: per-node lv prep + mask ----------------
__global__ void k1_prep(const float* __restrict__ lvs, const void* __restrict__ mask) {
    int gid = blockIdx.x * blockDim.x + threadIdx.x;
    if (gid >= BB * NN) return;
    int b = gid >> 10, n = gid & (NN - 1);
    int mode = g_maskmode;
    float m;
    if (mode == 0)      m = (((const float*)mask)[gid] != 0.f) ? 1.f : 0.f;
    else if (mode == 1) m = (((const int*)mask)[gid] != 0) ? 1.f : 0.f;
    else                m = (((const unsigned char*)mask)[gid] != 0) ? 1.f : 0.f;
    const float* base = lvs + b * 4 * NN + n;
    float px = base[0], py = base[NN], pz = base[2 * NN], e = base[3 * NN];
    float pt  = sqrtf(px * px + py * py);
    float rap = 0.5f * log1pf(2.f * pz / fmaxf(e - pz, 1e-20f));
    float phi = atan2f(py, px);
    float4* o = (float4*)(g_lvpack + gid * 8);
    o[0] = make_float4(px, py, pz, e);
    o[1] = make_float4(pt, rap, phi, m);
}

// ---------------- k2: knn top-16 ----------------
__global__ void k2_knn(const float* __restrict__ pts) {
    __shared__ float se[NN], sp[NN];
    int b  = blockIdx.x >> 3;
    int i0 = (blockIdx.x & 7) * 128;
    for (int q = threadIdx.x; q < NN; q += 128) {
        se[q] = pts[b * 2 * NN + q];
        sp[q] = pts[b * 2 * NN + NN + q];
    }
    __syncthreads();
    int i = i0 + threadIdx.x;
    float ei = se[i], pi = sp[i];
    float bd[KK]; int bj[KK];
#pragma unroll
    for (int q = 0; q < KK; q++) { bd[q] = 3.4e38f; bj[q] = 0; }
    for (int j = 0; j < NN; j++) {
        float de = ei - se[j];
        float dp = pi - sp[j] + PI_F;
        dp = fmodf(dp, TWOPI_F);
        if (dp < 0.f) dp += TWOPI_F;
        dp -= PI_F;
        float d = de * de + dp * dp;
        if (d < bd[KK - 1]) {
            float cd = d; int cj = j;
#pragma unroll
            for (int q = 0; q < KK; q++) {
                if (cd < bd[q]) {
                    float td = bd[q]; bd[q] = cd; cd = td;
                    int   tj = bj[q]; bj[q] = cj; cj = tj;
                }
            }
        }
    }
    int base = (b * NN + i) * KK;
#pragma unroll
    for (int q = 0; q < KK; q++) g_idx[base + q] = bj[q];
}

// ---------------- k3: node features -> u, v ----------------
__global__ void k3_nodeuv(const float* __restrict__ fts,
                          const float* __restrict__ bn1_s, const float* __restrict__ bn1_b,
                          const float* __restrict__ w_node,
                          const float* __restrict__ bn2_s, const float* __restrict__ bn2_b,
                          const float* __restrict__ w_e1) {
    extern __shared__ float sm3[];
    float* sw  = sm3;             // 128*128 : w_e1 cols 0..127
    float* swn = sw + 128 * 128;  // 64*32
    float* s1  = swn + 64 * 32;   // 32
    float* b1  = s1 + 32;         // 32
    float* s2  = b1 + 32;         // 128
    float* b2  = s2 + 128;        // 128
    int t = threadIdx.x;
    for (int q = t; q < 128 * 128; q += blockDim.x) {
        int o = q >> 7, c = q & 127;
        sw[q] = w_e1[o * 132 + c];
    }
    for (int q = t; q < 64 * 32; q += blockDim.x) swn[q] = w_node[q];
    if (t < 32) { s1[t] = bn1_s[t]; b1[t] = bn1_b[t]; }
    if (t < 128) { s2[t] = bn2_s[t]; b2[t] = bn2_b[t]; }
    __syncthreads();

    int gid = blockIdx.x * blockDim.x + t;
    int b = gid >> 10, n = gid & 1023;

    float a[32];
#pragma unroll
    for (int c = 0; c < 32; c++)
        a[c] = fmaxf(fts[(b * 32 + c) * NN + n] * s1[c] + b1[c], 0.f);

    float ra[64], rb[64];
    for (int c = 0; c < 64; c++) {
        float nv = 0.f;
        const float4* wv = (const float4*)(swn + c * 32);
#pragma unroll
        for (int q = 0; q < 8; q++) {
            float4 w = wv[q];
            nv += w.x * a[q * 4] + w.y * a[q * 4 + 1] + w.z * a[q * 4 + 2] + w.w * a[q * 4 + 3];
        }
        ra[c] = fmaxf(nv * s2[c] + b2[c], 0.f);
        rb[c] = fmaxf(nv * s2[64 + c] + b2[64 + c], 0.f);
    }

    float* up = g_u + gid * MSGD;
    float* vp = g_v + gid * MSGD;
    for (int o = 0; o < MSGD; o++) {
        const float4* wv = (const float4*)(sw + o * 128);
        float su = 0.f, sv = 0.f;
#pragma unroll
        for (int q = 0; q < 16; q++) {
            float4 w = wv[q];
            su += w.x * ra[q * 4] + w.y * ra[q * 4 + 1] + w.z * ra[q * 4 + 2] + w.w * ra[q * 4 + 3];
        }
#pragma unroll
        for (int q = 0; q < 16; q++) {
            float4 w = wv[16 + q];
            sv += w.x * rb[q * 4] + w.y * rb[q * 4 + 1] + w.z * rb[q * 4 + 2] + w.w * rb[q * 4 + 3];
        }
        up[o] = su;
        vp[o] = sv;
    }
}

// ---------------- k4: fused edge kernel ----------------
// Per block: 8 nodes x 16 neighbors = 128 edges.
// R[node][c] = sum_k valid * relu(bn3(u_i + v_j + Wc@relu(bn2c(lv4))))
// s[b, co, node] = w_e2[co,:] @ R[node,:]   (written into d_out as scratch)
__global__ void k4_edge(const float* __restrict__ w_e1,
                        const float* __restrict__ bn2_s, const float* __restrict__ bn2_b,
                        const float* __restrict__ bn3_s, const float* __restrict__ bn3_b,
                        const float* __restrict__ w_e2,
                        float* __restrict__ outp) {
    extern __shared__ float sm4[];
    float* sw2 = sm4;                 // 128*132 (padded rows, conflict-free)
    float* R_s = sw2 + 128 * 132;     // 8*132
    float* rlv = R_s + 8 * 132;       // 128*4
    float* vld = rlv + 512;           // 128
    int*   js  = (int*)(vld + 128);   // 128

    int t  = threadIdx.x;
    int b  = blockIdx.x >> 7;
    int i0 = (blockIdx.x & 127) * 8;

    for (int q = t; q < 128 * 128; q += 256) {
        int o = q >> 7, c = q & 127;
        sw2[o * 132 + c] = w_e2[q];
    }
    if (t < 128) js[t] = g_idx[(b * NN + i0) * KK + t];
    __syncthreads();

    if (t < 128) {
        int e = t, nl = e >> 4;
        int i = i0 + nl, j = js[e];
        const float4* Li = (const float4*)(g_lvpack + (b * NN + i) * 8);
        const float4* Lj = (const float4*)(g_lvpack + (b * NN + j) * 8);
        float4 A0 = Li[0], A1 = Li[1], B0 = Lj[0], B1 = Lj[1];
        float pti = A1.x, ptj = B1.x;
        float ptmin = fminf(pti, ptj);
        float dphi = A1.z - B1.z + PI_F;
        dphi = fmodf(dphi, TWOPI_F);
        if (dphi < 0.f) dphi += TWOPI_F;
        dphi -= PI_F;
        float drap  = A1.y - B1.y;
        float delta = sqrtf(drap * drap + dphi * dphi);
        float lndelta = logf(fmaxf(delta, EPS_F));
        float lnkt    = logf(fmaxf(ptmin * delta, EPS_F));
        float lnz     = logf(fmaxf(ptmin / fmaxf(pti + ptj, EPS_F), EPS_F));
        float sx = A0.x + B0.x, sy = A0.y + B0.y, sz = A0.z + B0.z, s4 = A0.w + B0.w;
        float lnm2 = logf(fmaxf(s4 * s4 - (sx * sx + sy * sy + sz * sz), EPS_F));
        float lv[4] = {lnkt, lnz, lndelta, lnm2};
#pragma unroll
        for (int f = 0; f < 4; f++)
            rlv[e * 4 + f] = fmaxf(lv[f] * __ldg(bn2_s + 128 + f) + __ldg(bn2_b + 128 + f), 0.f);
        vld[e] = A1.w * B1.w;
    }
    __syncthreads();

    if (t < 8) {
        float c = 0.f;
#pragma unroll
        for (int k = 0; k < KK; k++) c += vld[t * 16 + k];
        g_cnt[b * NN + i0 + t] = c;
    }

    // phase b: accumulate R over k
    {
        int nl = t >> 5, c4 = (t & 31) * 4;
        float4 u4 = *(const float4*)(g_u + ((b * NN + i0 + nl) * MSGD + c4));
        float wc[4][4], s3[4], b3[4];
#pragma unroll
        for (int q = 0; q < 4; q++) {
            s3[q] = __ldg(bn3_s + c4 + q);
            b3[q] = __ldg(bn3_b + c4 + q);
#pragma unroll
            for (int f = 0; f < 4; f++) wc[q][f] = __ldg(w_e1 + (c4 + q) * 132 + 128 + f);
        }
        float a0 = 0.f, a1 = 0.f, a2 = 0.f, a3 = 0.f;
#pragma unroll
        for (int k = 0; k < KK; k++) {
            int e = (nl << 4) | k;
            int j = js[e];
            float4 v4 = *(const float4*)(g_v + ((b * NN + j) * MSGD + c4));
            float l0 = rlv[e * 4], l1 = rlv[e * 4 + 1], l2 = rlv[e * 4 + 2], l3 = rlv[e * 4 + 3];
            float val = vld[e];
            float h0 = u4.x + v4.x + wc[0][0] * l0 + wc[0][1] * l1 + wc[0][2] * l2 + wc[0][3] * l3;
            float h1 = u4.y + v4.y + wc[1][0] * l0 + wc[1][1] * l1 + wc[1][2] * l2 + wc[1][3] * l3;
            float h2 = u4.z + v4.z + wc[2][0] * l0 + wc[2][1] * l1 + wc[2][2] * l2 + wc[2][3] * l3;
            float h3 = u4.w + v4.w + wc[3][0] * l0 + wc[3][1] * l1 + wc[3][2] * l2 + wc[3][3] * l3;
            a0 += fmaxf(h0 * s3[0] + b3[0], 0.f) * val;
            a1 += fmaxf(h1 * s3[1] + b3[1], 0.f) * val;
            a2 += fmaxf(h2 * s3[2] + b3[2], 0.f) * val;
            a3 += fmaxf(h3 * s3[3] + b3[3], 0.f) * val;
        }
        R_s[nl * 132 + c4 + 0] = a0;
        R_s[nl * 132 + c4 + 1] = a1;
        R_s[nl * 132 + c4 + 2] = a2;
        R_s[nl * 132 + c4 + 3] = a3;
    }
    __syncthreads();

    // phase c: s = w_e2 @ R, write to d_out scratch
    {
        int co = t >> 1, nb = (t & 1) * 4;
        float a0 = 0.f, a1 = 0.f, a2 = 0.f, a3 = 0.f;
        const float4* wv = (const float4*)(sw2 + co * 132);
#pragma unroll 8
        for (int cc = 0; cc < 32; cc++) {
            float4 w  = wv[cc];
            float4 r0 = *(const float4*)(R_s + (nb + 0) * 132 + cc * 4);
            float4 r1 = *(const float4*)(R_s + (nb + 1) * 132 + cc * 4);
            float4 r2 = *(const float4*)(R_s + (nb + 2) * 132 + cc * 4);
            float4 r3 = *(const float4*)(R_s + (nb + 3) * 132 + cc * 4);
            a0 += w.x * r0.x + w.y * r0.y + w.z * r0.z + w.w * r0.w;
            a1 += w.x * r1.x + w.y * r1.y + w.z * r1.z + w.w * r1.w;
            a2 += w.x * r2.x + w.y * r2.y + w.z * r2.z + w.w * r2.w;
            a3 += w.x * r3.x + w.y * r3.y + w.z * r3.z + w.w * r3.w;
        }
        *(float4*)(outp + (b * MSGD + co) * NN + i0 + nb) = make_float4(a0, a1, a2, a3);
    }
}

// ---------------- k5: S[b,c] = sum_i s ----------------
__global__ void k5_reduceS(const float* __restrict__ outp) {
    int row  = blockIdx.x * 8 + (threadIdx.x >> 5);
    int lane = threadIdx.x & 31;
    const float* p = outp + row * NN;
    float s = 0.f;
    for (int q = lane; q < NN; q += 32) s += p[q];
#pragma unroll
    for (int o = 16; o > 0; o >>= 1) s += __shfl_down_sync(0xffffffffu, s, o);
    if (lane == 0) g_S[row] = s;
}

__global__ void k5b_reduceN() {
    int b = threadIdx.x >> 5, lane = threadIdx.x & 31;
    float s = 0.f;
    for (int q = lane; q < NN; q += 32) s += g_cnt[b * NN + q];
#pragma unroll
    for (int o = 16; o > 0; o >>= 1) s += __shfl_down_sync(0xffffffffu, s, o);
    if (lane == 0) g_nb[b] = s;
}

// ---------------- k6: SE gate ----------------
__global__ void k6_se(const float* __restrict__ w1, const float* __restrict__ w2) {
    __shared__ float pooled[128];
    __shared__ float tv[8];
    int b = blockIdx.x, t = threadIdx.x;
    float nv = g_nb[b];
    float nd = (nv == 0.f) ? 1.f : nv;
    pooled[t] = g_S[b * 128 + t] / nd;
    __syncthreads();
    if (t < 8) {
        float s = 0.f;
        for (int c = 0; c < 128; c++) s += pooled[c] * w1[t * 128 + c];
        tv[t] = fmaxf(s, 0.f);
    }
    __syncthreads();
    float z = 0.f;
#pragma unroll
    for (int o = 0; o < 8; o++) z += tv[o] * w2[t * 8 + o];
    g_y[b * 128 + t] = 1.f / (1.f + expf(-z));
}

// ---------------- k7: final scale ----------------
__global__ void k7_final(float* __restrict__ outp) {
    int idx = blockIdx.x * blockDim.x + threadIdx.x;
    if (idx >= BB * MSGD * NN / 4) return;
    int flat = idx * 4;
    int i    = flat & 1023;
    int row  = flat >> 10;           // = b*128 + c
    float y  = g_y[row];
    const float* cp = g_cnt + (row >> 7) * NN + i;
    float4 v = ((float4*)outp)[idx];
    v.x *= y / fmaxf(cp[0], 1.f);
    v.y *= y / fmaxf(cp[1], 1.f);
    v.z *= y / fmaxf(cp[2], 1.f);
    v.w *= y / fmaxf(cp[3], 1.f);
    ((float4*)outp)[idx] = v;
}

extern "C" void kernel_launch(void* const* d_in, const int* in_sizes, int n_in,
                              void* d_out, int out_size) {
    const float* pts   = (const float*)d_in[0];
    const float* fts   = (const float*)d_in[1];
    const float* lvs   = (const float*)d_in[2];
    const void*  mask  = d_in[3];
    const float* bn1_s = (const float*)d_in[4];
    const float* bn1_b = (const float*)d_in[5];
    const float* w_node= (const float*)d_in[6];
    const float* bn2_s = (const float*)d_in[7];
    const float* bn2_b = (const float*)d_in[8];
    const float* w_e1  = (const float*)d_in[9];
    const float* bn3_s = (const float*)d_in[10];
    const float* bn3_b = (const float*)d_in[11];
    const float* w_e2  = (const float*)d_in[12];
    const float* se_w1 = (const float*)d_in[13];
    const float* se_w2 = (const float*)d_in[14];
    float* outp = (float*)d_out;

    cudaFuncSetAttribute(k3_nodeuv, cudaFuncAttributeMaxDynamicSharedMemorySize, 75008);
    cudaFuncSetAttribute(k4_edge,   cudaFuncAttributeMaxDynamicSharedMemorySize, 74880);

    k0_detect<<<1, 32>>>((const unsigned int*)mask);
    k1_prep<<<64, 256>>>(lvs, mask);
    k2_knn<<<128, 128>>>(pts);
    k3_nodeuv<<<128, 128, 75008>>>(fts, bn1_s, bn1_b, w_node, bn2_s, bn2_b, w_e1);
    k4_edge<<<2048, 256, 74880>>>(w_e1, bn2_s, bn2_b, bn3_s, bn3_b, w_e2, outp);
    k5_reduceS<<<256, 256>>>(outp);
    k5b_reduceN<<<1, 512>>>();
    k6_se<<<16, 128>>>(se_w1, se_w2);
    k7_final<<<512, 1024>>>(outp);
}

// round 2
// speedup vs baseline: 1.8507x; 1.8507x over previous
#include <cuda_runtime.h>
#include <math.h>

#define BB 16
#define NN 1024
#define KK 16
#define MSGD 128
#define PI_F 3.14159265358979323846f
#define TWOPI_F 6.28318530717958647692f
#define INV_TWOPI_F 0.15915494309189533577f
#define EPS_F 1e-8f

// ---------------- device scratch ----------------
__device__ int   g_maskmode;
__device__ __align__(16) float g_lvpack[BB*NN*8];   // px,py,pz,e,pt,rap,phi,mask
__device__ int   g_idx[BB*NN*KK];
__device__ __align__(16) float g_u[BB*NN*MSGD];     // node-major
__device__ __align__(16) float g_v[BB*NN*MSGD];
__device__ __align__(16) float g_R[BB*NN*MSGD];     // per-node k-summed message
__device__ __align__(16) float g_cnt[BB*NN];
__device__ float g_Pp[BB*8*MSGD];
__device__ float g_nbp[BB*8];
__device__ float g_y[BB*MSGD];

// ---------------- k0: detect mask dtype ----------------
__global__ void k0_detect(const unsigned int* mw) {
    if (threadIdx.x == 0) {
        int allf = 1, alli = 1;
        for (int q = 0; q < 64; q++) {
            unsigned int w = mw[q];
            if (!(w == 0u || w == 0x3F800000u)) allf = 0;
            if (!(w == 0u || w == 1u))          alli = 0;
        }
        g_maskmode = allf ? 0 : (alli ? 1 : 2);
    }
}

// ---------------- k1: per-node lv prep + mask ----------------
__global__ void k1_prep(const float* __restrict__ lvs, const void* __restrict__ mask) {
    int gid = blockIdx.x * blockDim.x + threadIdx.x;
    if (gid >= BB * NN) return;
    int b = gid >> 10, n = gid & (NN - 1);
    int mode = g_maskmode;
    float m;
    if (mode == 0)      m = (((const float*)mask)[gid] != 0.f) ? 1.f : 0.f;
    else if (mode == 1) m = (((const int*)mask)[gid] != 0) ? 1.f : 0.f;
    else                m = (((const unsigned char*)mask)[gid] != 0) ? 1.f : 0.f;
    const float* base = lvs + b * 4 * NN + n;
    float px = base[0], py = base[NN], pz = base[2 * NN], e = base[3 * NN];
    float pt  = sqrtf(px * px + py * py);
    float rap = 0.5f * log1pf(2.f * pz / fmaxf(e - pz, 1e-20f));
    float phi = atan2f(py, px);
    float4* o = (float4*)(g_lvpack + gid * 8);
    o[0] = make_float4(px, py, pz, e);
    o[1] = make_float4(pt, rap, phi, m);
}

// ---------------- k2: knn top-16, 2 threads per node + merge ----------------
__global__ void k2_knn(const float* __restrict__ pts) {
    __shared__ float se[NN], sp[NN];
    __shared__ float md[256 * 16];
    __shared__ int   mj[256 * 16];
    int t  = threadIdx.x;
    int b  = blockIdx.x >> 3;
    int i0 = (blockIdx.x & 7) * 128;
    for (int q = t; q < NN; q += 256) {
        se[q] = pts[b * 2 * NN + q];
        sp[q] = pts[b * 2 * NN + NN + q];
    }
    __syncthreads();
    int il = t & 127, half = t >> 7;
    float ei = se[i0 + il], pii = sp[i0 + il];
    float bd[KK]; int bj[KK];
#pragma unroll
    for (int q = 0; q < KK; q++) { bd[q] = 3.4e38f; bj[q] = 0; }
    int j0 = half * 512;
    for (int jj = 0; jj < 512; jj++) {
        int j = j0 + jj;
        float de = ei - se[j];
        float dp = pii - sp[j];
        dp -= TWOPI_F * rintf(dp * INV_TWOPI_F);
        float d = de * de + dp * dp;
        if (d < bd[KK - 1]) {
            float cd = d; int cj = j;
#pragma unroll
            for (int q = 0; q < KK; q++) {
                if (cd < bd[q]) {
                    float td = bd[q]; bd[q] = cd; cd = td;
                    int   tj = bj[q]; bj[q] = cj; cj = tj;
                }
            }
        }
    }
#pragma unroll
    for (int q = 0; q < KK; q++) { md[t * 16 + q] = bd[q]; mj[t * 16 + q] = bj[q]; }
    __syncthreads();
    if (t < 128) {
        int pa = 0, pb = 0;
        int baseA = t * 16, baseB = (t + 128) * 16;
        int obase = (b * NN + i0 + t) * KK;
#pragma unroll
        for (int q = 0; q < KK; q++) {
            float dA = md[baseA + pa], dB = md[baseB + pb];
            if (dB < dA) { g_idx[obase + q] = mj[baseB + pb]; pb++; }
            else         { g_idx[obase + q] = mj[baseA + pa]; pa++; }
        }
    }
}

// ---------------- k3: node features -> u, v (block GEMM, 64 nodes/block) ----------------
__global__ void k3_nodeuv(const float* __restrict__ fts,
                          const float* __restrict__ bn1_s, const float* __restrict__ bn1_b,
                          const float* __restrict__ w_node,
                          const float* __restrict__ bn2_s, const float* __restrict__ bn2_b,
                          const float* __restrict__ w_e1) {
    extern __shared__ float sm3[];
    float* a_s  = sm3;                 // [32][64]
    float* ra_s = a_s + 32 * 64;       // [64][68]
    float* rb_s = ra_s + 64 * 68;      // [64][68]
    float* w_s  = rb_s + 64 * 68;      // [128][68]  (also holds w_node first)
    int t   = threadIdx.x;
    int gn0 = blockIdx.x * 64;
    int b   = gn0 >> 10;
    int n0  = gn0 & (NN - 1);

    for (int q = t; q < 2048; q += 256) {
        int c = q >> 6, n = q & 63;
        float v = fts[(b * 32 + c) * NN + n0 + n];
        a_s[q] = fmaxf(v * __ldg(bn1_s + c) + __ldg(bn1_b + c), 0.f);
    }
    for (int q = t; q < 2048; q += 256) w_s[q] = w_node[q];
    __syncthreads();

    {   // nv + dual bn2 -> ra/rb
        int node = t & 63, quarter = t >> 6;
        float av[32];
#pragma unroll
        for (int c = 0; c < 32; c++) av[c] = a_s[c * 64 + node];
#pragma unroll
        for (int oo = 0; oo < 16; oo++) {
            int o = quarter * 16 + oo;
            const float* wr = w_s + o * 32;
            float nv = 0.f;
#pragma unroll
            for (int c = 0; c < 32; c++) nv += wr[c] * av[c];
            ra_s[o * 68 + node] = fmaxf(nv * __ldg(bn2_s + o)      + __ldg(bn2_b + o), 0.f);
            rb_s[o * 68 + node] = fmaxf(nv * __ldg(bn2_s + 64 + o) + __ldg(bn2_b + 64 + o), 0.f);
        }
    }
    __syncthreads();

    int ng = t & 7, cg = t >> 3;          // 8 node-groups x 32 channel-groups
    float acc[8][4];

    // ---- U pass ----
    for (int q = t; q < 2048; q += 256) {
        int o = q >> 4, k4 = (q & 15) << 2;
        float4 w4 = *(const float4*)(w_e1 + o * 132 + k4);
        *(float4*)(w_s + o * 68 + k4) = w4;
    }
    __syncthreads();
#pragma unroll
    for (int j = 0; j < 8; j++)
#pragma unroll
        for (int c = 0; c < 4; c++) acc[j][c] = 0.f;
#pragma unroll 4
    for (int k = 0; k < 64; k++) {
        float4 r0 = *(const float4*)(ra_s + k * 68 + ng * 8);
        float4 r1 = *(const float4*)(ra_s + k * 68 + ng * 8 + 4);
        float w0 = w_s[(cg * 4 + 0) * 68 + k];
        float w1 = w_s[(cg * 4 + 1) * 68 + k];
        float w2 = w_s[(cg * 4 + 2) * 68 + k];
        float w3 = w_s[(cg * 4 + 3) * 68 + k];
        float rj[8] = {r0.x, r0.y, r0.z, r0.w, r1.x, r1.y, r1.z, r1.w};
#pragma unroll
        for (int j = 0; j < 8; j++) {
            acc[j][0] += rj[j] * w0; acc[j][1] += rj[j] * w1;
            acc[j][2] += rj[j] * w2; acc[j][3] += rj[j] * w3;
        }
    }
#pragma unroll
    for (int j = 0; j < 8; j++)
        *(float4*)(g_u + (gn0 + ng * 8 + j) * MSGD + cg * 4) =
            make_float4(acc[j][0], acc[j][1], acc[j][2], acc[j][3]);
    __syncthreads();

    // ---- V pass ----
    for (int q = t; q < 2048; q += 256) {
        int o = q >> 4, k4 = (q & 15) << 2;
        float4 w4 = *(const float4*)(w_e1 + o * 132 + 64 + k4);
        *(float4*)(w_s + o * 68 + k4) = w4;
    }
    __syncthreads();
#pragma unroll
    for (int j = 0; j < 8; j++)
#pragma unroll
        for (int c = 0; c < 4; c++) acc[j][c] = 0.f;
#pragma unroll 4
    for (int k = 0; k < 64; k++) {
        float4 r0 = *(const float4*)(rb_s + k * 68 + ng * 8);
        float4 r1 = *(const float4*)(rb_s + k * 68 + ng * 8 + 4);
        float w0 = w_s[(cg * 4 + 0) * 68 + k];
        float w1 = w_s[(cg * 4 + 1) * 68 + k];
        float w2 = w_s[(cg * 4 + 2) * 68 + k];
        float w3 = w_s[(cg * 4 + 3) * 68 + k];
        float rj[8] = {r0.x, r0.y, r0.z, r0.w, r1.x, r1.y, r1.z, r1.w};
#pragma unroll
        for (int j = 0; j < 8; j++) {
            acc[j][0] += rj[j] * w0; acc[j][1] += rj[j] * w1;
            acc[j][2] += rj[j] * w2; acc[j][3] += rj[j] * w3;
        }
    }
#pragma unroll
    for (int j = 0; j < 8; j++)
        *(float4*)(g_v + (gn0 + ng * 8 + j) * MSGD + cg * 4) =
            make_float4(acc[j][0], acc[j][1], acc[j][2], acc[j][3]);
}

// ---------------- k4: fused edge kernel -> R (no w_e2 here) ----------------
__global__ void k4_edge(const float* __restrict__ w_e1,
                        const float* __restrict__ bn2_s, const float* __restrict__ bn2_b,
                        const float* __restrict__ bn3_s, const float* __restrict__ bn3_b) {
    __shared__ int   js[256];
    __shared__ float rlv[256 * 4];
    __shared__ float vld[256];
    __shared__ float wc4[128 * 5];
    __shared__ float s3s[128], b3s[128];
    __shared__ float s2l[4], b2l[4];
    int t  = threadIdx.x;
    int b  = blockIdx.x >> 6;
    int i0 = (blockIdx.x & 63) * 16;

    js[t] = g_idx[(b * NN + i0) * KK + t];
    if (t < 128) {
#pragma unroll
        for (int f = 0; f < 4; f++) wc4[t * 5 + f] = w_e1[t * 132 + 128 + f];
        s3s[t] = bn3_s[t]; b3s[t] = bn3_b[t];
    }
    if (t < 4) { s2l[t] = bn2_s[128 + t]; b2l[t] = bn2_b[128 + t]; }
    __syncthreads();

    {   // per-edge lv features
        int e = t;
        int i = i0 + (e >> 4), j = js[e];
        const float4* Li = (const float4*)(g_lvpack + (b * NN + i) * 8);
        const float4* Lj = (const float4*)(g_lvpack + (b * NN + j) * 8);
        float4 A0 = Li[0], A1 = Li[1], B0 = Lj[0], B1 = Lj[1];
        float pti = A1.x, ptj = B1.x;
        float ptmin = fminf(pti, ptj);
        float dphi = A1.z - B1.z;
        dphi -= TWOPI_F * rintf(dphi * INV_TWOPI_F);
        float drap  = A1.y - B1.y;
        float delta = sqrtf(drap * drap + dphi * dphi);
        float lndelta = logf(fmaxf(delta, EPS_F));
        float lnkt    = logf(fmaxf(ptmin * delta, EPS_F));
        float lnz     = logf(fmaxf(ptmin / fmaxf(pti + ptj, EPS_F), EPS_F));
        float sx = A0.x + B0.x, sy = A0.y + B0.y, sz = A0.z + B0.z, s4 = A0.w + B0.w;
        float lnm2 = logf(fmaxf(s4 * s4 - (sx * sx + sy * sy + sz * sz), EPS_F));
        float lv[4] = {lnkt, lnz, lndelta, lnm2};
#pragma unroll
        for (int f = 0; f < 4; f++)
            rlv[e * 4 + f] = fmaxf(lv[f] * s2l[f] + b2l[f], 0.f);
        vld[e] = A1.w * B1.w;
    }
    __syncthreads();

    if (t < 16) {
        float c = 0.f;
#pragma unroll
        for (int k = 0; k < KK; k++) c += vld[t * 16 + k];
        g_cnt[b * NN + i0 + t] = c;
    }

    int nl = t >> 4, c8 = (t & 15) << 3;
    int gi = b * NN + i0 + nl;
    float4 u0 = *(const float4*)(g_u + gi * MSGD + c8);
    float4 u1 = *(const float4*)(g_u + gi * MSGD + c8 + 4);
    float ur[8] = {u0.x, u0.y, u0.z, u0.w, u1.x, u1.y, u1.z, u1.w};
    float wcr[8][4], s3r[8], b3r[8];
#pragma unroll
    for (int q = 0; q < 8; q++) {
        s3r[q] = s3s[c8 + q]; b3r[q] = b3s[c8 + q];
#pragma unroll
        for (int f = 0; f < 4; f++) wcr[q][f] = wc4[(c8 + q) * 5 + f];
    }
    float acc[8] = {0.f, 0.f, 0.f, 0.f, 0.f, 0.f, 0.f, 0.f};
#pragma unroll
    for (int k = 0; k < KK; k++) {
        int e = (nl << 4) | k;
        int j = js[e];
        const float* vp = g_v + (b * NN + j) * MSGD + c8;
        float4 v0 = *(const float4*)vp;
        float4 v1 = *(const float4*)(vp + 4);
        float vr[8] = {v0.x, v0.y, v0.z, v0.w, v1.x, v1.y, v1.z, v1.w};
        float l0 = rlv[e * 4], l1 = rlv[e * 4 + 1], l2 = rlv[e * 4 + 2], l3 = rlv[e * 4 + 3];
        float val = vld[e];
#pragma unroll
        for (int q = 0; q < 8; q++) {
            float h = ur[q] + vr[q] + wcr[q][0] * l0 + wcr[q][1] * l1
                    + wcr[q][2] * l2 + wcr[q][3] * l3;
            acc[q] += fmaxf(h * s3r[q] + b3r[q], 0.f) * val;
        }
    }
    *(float4*)(g_R + gi * MSGD + c8)     = make_float4(acc[0], acc[1], acc[2], acc[3]);
    *(float4*)(g_R + gi * MSGD + c8 + 4) = make_float4(acc[4], acc[5], acc[6], acc[7]);
}

// ---------------- k_red: partial pool of R and cnt ----------------
__global__ void k_red() {   // grid 128 (b x chunk), block 128
    int b = blockIdx.x >> 3, ch = blockIdx.x & 7;
    int t = threadIdx.x;
    const float* base = g_R + (b * NN + ch * 128) * MSGD + t;
    float s0 = 0.f, s1 = 0.f, s2 = 0.f, s3 = 0.f;
#pragma unroll 4
    for (int i = 0; i < 128; i += 4) {
        s0 += base[(i + 0) * MSGD]; s1 += base[(i + 1) * MSGD];
        s2 += base[(i + 2) * MSGD]; s3 += base[(i + 3) * MSGD];
    }
    g_Pp[(b * 8 + ch) * MSGD + t] = s0 + s1 + s2 + s3;

    float c = g_cnt[b * NN + ch * 128 + t];
    __shared__ float cs[4];
#pragma unroll
    for (int o = 16; o > 0; o >>= 1) c += __shfl_down_sync(0xffffffffu, c, o);
    if ((t & 31) == 0) cs[t >> 5] = c;
    __syncthreads();
    if (t == 0) g_nbp[b * 8 + ch] = cs[0] + cs[1] + cs[2] + cs[3];
}

// ---------------- k6: SE gate (pool = w_e2 @ P / n) ----------------
__global__ void k6_se(const float* __restrict__ w_e2,
                      const float* __restrict__ w1, const float* __restrict__ w2) {
    __shared__ float pooled[128], spool[128], tv[8];
    __shared__ float nd_s;
    int b = blockIdx.x, t = threadIdx.x;
    float s = 0.f;
#pragma unroll
    for (int ch = 0; ch < 8; ch++) s += g_Pp[(b * 8 + ch) * MSGD + t];
    pooled[t] = s;
    if (t == 0) {
        float n = 0.f;
#pragma unroll
        for (int ch = 0; ch < 8; ch++) n += g_nbp[b * 8 + ch];
        nd_s = (n == 0.f) ? 1.f : n;
    }
    __syncthreads();
    float nd = nd_s;
    const float* wr = w_e2 + t * 128;
    float d = 0.f;
#pragma unroll 4
    for (int c = 0; c < 128; c++) d += wr[c] * pooled[c];
    spool[t] = d / nd;
    __syncthreads();
    if (t < 8) {
        float z = 0.f;
        for (int c = 0; c < 128; c++) z += w1[t * 128 + c] * spool[c];
        tv[t] = fmaxf(z, 0.f);
    }
    __syncthreads();
    float z = 0.f;
#pragma unroll
    for (int o = 0; o < 8; o++) z += tv[o] * w2[t * 8 + o];
    g_y[b * 128 + t] = 1.f / (1.f + expf(-z));
}

// ---------------- k5: out = diag(y) * w_e2 @ R^T * diag(1/cnt) ----------------
__global__ void k5_out(const float* __restrict__ w_e2, float* __restrict__ outp) {
    extern __shared__ float sm5[];
    float* w_s = sm5;             // [64][132] k-major
    float* r_s = sm5 + 64 * 132;  // [64][132]
    int t   = threadIdx.x;
    int gn0 = blockIdx.x * 128;
    int b   = gn0 >> 10;
    int nn0 = gn0 & (NN - 1);
    int cg = t >> 4, ng = t & 15;   // 16 co-groups x 16 node-groups, 8x8 each
    float acc[8][8];
#pragma unroll
    for (int i = 0; i < 8; i++)
#pragma unroll
        for (int j = 0; j < 8; j++) acc[i][j] = 0.f;

    for (int k0 = 0; k0 < 128; k0 += 64) {
        for (int q = t; q < 2048; q += 256) {
            int co = q >> 4, k4 = (q & 15) << 2;
            float4 w4 = *(const float4*)(w_e2 + co * 128 + k0 + k4);
            w_s[(k4 + 0) * 132 + co] = w4.x;
            w_s[(k4 + 1) * 132 + co] = w4.y;
            w_s[(k4 + 2) * 132 + co] = w4.z;
            w_s[(k4 + 3) * 132 + co] = w4.w;
        }
        for (int q = t; q < 2048; q += 256) {
            int n = q >> 4, k4 = (q & 15) << 2;
            float4 r4 = *(const float4*)(g_R + (gn0 + n) * MSGD + k0 + k4);
            r_s[(k4 + 0) * 132 + n] = r4.x;
            r_s[(k4 + 1) * 132 + n] = r4.y;
            r_s[(k4 + 2) * 132 + n] = r4.z;
            r_s[(k4 + 3) * 132 + n] = r4.w;
        }
        __syncthreads();
#pragma unroll 4
        for (int k = 0; k < 64; k++) {
            float4 wa = *(const float4*)(w_s + k * 132 + cg * 8);
            float4 wb = *(const float4*)(w_s + k * 132 + cg * 8 + 4);
            float4 rA = *(const float4*)(r_s + k * 132 + ng * 8);
            float4 rB = *(const float4*)(r_s + k * 132 + ng * 8 + 4);
            float wv[8] = {wa.x, wa.y, wa.z, wa.w, wb.x, wb.y, wb.z, wb.w};
            float rv[8] = {rA.x, rA.y, rA.z, rA.w, rB.x, rB.y, rB.z, rB.w};
#pragma unroll
            for (int i = 0; i < 8; i++)
#pragma unroll
                for (int j = 0; j < 8; j++) acc[i][j] += wv[i] * rv[j];
        }
        __syncthreads();
    }

    float yv[8], rcv[8];
#pragma unroll
    for (int i = 0; i < 8; i++) yv[i] = g_y[b * 128 + cg * 8 + i];
#pragma unroll
    for (int j = 0; j < 8; j++)
        rcv[j] = 1.f / fmaxf(g_cnt[b * NN + nn0 + ng * 8 + j], 1.f);
#pragma unroll
    for (int i = 0; i < 8; i++) {
        float sc = yv[i];
        float* op = outp + (b * 128 + cg * 8 + i) * NN + nn0 + ng * 8;
        *(float4*)op = make_float4(acc[i][0] * sc * rcv[0], acc[i][1] * sc * rcv[1],
                                   acc[i][2] * sc * rcv[2], acc[i][3] * sc * rcv[3]);
        *(float4*)(op + 4) = make_float4(acc[i][4] * sc * rcv[4], acc[i][5] * sc * rcv[5],
                                         acc[i][6] * sc * rcv[6], acc[i][7] * sc * rcv[7]);
    }
}

extern "C" void kernel_launch(void* const* d_in, const int* in_sizes, int n_in,
                              void* d_out, int out_size) {
    const float* pts   = (const float*)d_in[0];
    const float* fts   = (const float*)d_in[1];
    const float* lvs   = (const float*)d_in[2];
    const void*  mask  = d_in[3];
    const float* bn1_s = (const float*)d_in[4];
    const float* bn1_b = (const float*)d_in[5];
    const float* w_node= (const float*)d_in[6];
    const float* bn2_s = (const float*)d_in[7];
    const float* bn2_b = (const float*)d_in[8];
    const float* w_e1  = (const float*)d_in[9];
    const float* bn3_s = (const float*)d_in[10];
    const float* bn3_b = (const float*)d_in[11];
    const float* w_e2  = (const float*)d_in[12];
    const float* se_w1 = (const float*)d_in[13];
    const float* se_w2 = (const float*)d_in[14];
    float* outp = (float*)d_out;

    cudaFuncSetAttribute(k3_nodeuv, cudaFuncAttributeMaxDynamicSharedMemorySize, 77824);
    cudaFuncSetAttribute(k5_out,    cudaFuncAttributeMaxDynamicSharedMemorySize, 67584);

    k0_detect<<<1, 32>>>((const unsigned int*)mask);
    k1_prep<<<64, 256>>>(lvs, mask);
    k2_knn<<<128, 256>>>(pts);
    k3_nodeuv<<<256, 256, 77824>>>(fts, bn1_s, bn1_b, w_node, bn2_s, bn2_b, w_e1);
    k4_edge<<<1024, 256>>>(w_e1, bn2_s, bn2_b, bn3_s, bn3_b);
    k_red<<<128, 128>>>();
    k6_se<<<16, 128>>>(w_e2, se_w1, se_w2);
    k5_out<<<128, 256, 67584>>>(w_e2, outp);
}

// round 3
// speedup vs baseline: 1.8686x; 1.0097x over previous
#include <cuda_runtime.h>
#include <math.h>

#define BB 16
#define NN 1024
#define KK 16
#define MSGD 128
#define PI_F 3.14159265358979323846f
#define TWOPI_F 6.28318530717958647692f
#define INV_TWOPI_F 0.15915494309189533577f
#define EPS_F 1e-8f

// ---------------- device scratch ----------------
__device__ int   g_maskmode;
__device__ __align__(16) float g_lvpack[BB*NN*8];   // px,py,pz,e,pt,rap,phi,mask
__device__ int   g_idx[BB*NN*KK];
__device__ __align__(16) float g_u[BB*NN*MSGD];     // node-major
__device__ __align__(16) float g_v[BB*NN*MSGD];
__device__ __align__(16) float g_R[BB*NN*MSGD];     // per-node k-summed message
__device__ __align__(16) float g_cnt[BB*NN];
__device__ float g_Pp[BB*64*MSGD];                  // per-edge-block partial pools
__device__ float g_nbp[BB*64];
__device__ float g_y[BB*MSGD];

__device__ __forceinline__ float wrap_dphi(float x) {
    // matches jnp.mod(x + pi, 2pi) - pi  (python mod semantics)
    float xp = x + PI_F;
    return xp - floorf(xp * INV_TWOPI_F) * TWOPI_F - PI_F;
}

// ---------------- k0: detect mask dtype ----------------
__global__ void k0_detect(const unsigned int* mw) {
    if (threadIdx.x == 0) {
        int allf = 1, alli = 1;
        for (int q = 0; q < 64; q++) {
            unsigned int w = mw[q];
            if (!(w == 0u || w == 0x3F800000u)) allf = 0;
            if (!(w == 0u || w == 1u))          alli = 0;
        }
        g_maskmode = allf ? 0 : (alli ? 1 : 2);
    }
}

// ---------------- k1: per-node lv prep + mask ----------------
__global__ void k1_prep(const float* __restrict__ lvs, const void* __restrict__ mask) {
    int gid = blockIdx.x * blockDim.x + threadIdx.x;
    if (gid >= BB * NN) return;
    int b = gid >> 10, n = gid & (NN - 1);
    int mode = g_maskmode;
    float m;
    if (mode == 0)      m = (((const float*)mask)[gid] != 0.f) ? 1.f : 0.f;
    else if (mode == 1) m = (((const int*)mask)[gid] != 0) ? 1.f : 0.f;
    else                m = (((const unsigned char*)mask)[gid] != 0) ? 1.f : 0.f;
    const float* base = lvs + b * 4 * NN + n;
    float px = base[0], py = base[NN], pz = base[2 * NN], e = base[3 * NN];
    float pt  = sqrtf(px * px + py * py);
    float rap = 0.5f * log1pf(2.f * pz / fmaxf(e - pz, 1e-20f));
    float phi = atan2f(py, px);
    float4* o = (float4*)(g_lvpack + gid * 8);
    o[0] = make_float4(px, py, pz, e);
    o[1] = make_float4(pt, rap, phi, m);
}

// ---------------- k2: knn top-16, 2 threads per node + merge ----------------
__global__ void k2_knn(const float* __restrict__ pts) {
    __shared__ float se[NN], sp[NN];
    __shared__ float md[256 * 16];
    __shared__ int   mj[256 * 16];
    int t  = threadIdx.x;
    int b  = blockIdx.x >> 3;
    int i0 = (blockIdx.x & 7) * 128;
    for (int q = t; q < NN; q += 256) {
        se[q] = pts[b * 2 * NN + q];
        sp[q] = pts[b * 2 * NN + NN + q];
    }
    __syncthreads();
    int il = t & 127, half = t >> 7;
    float ei = se[i0 + il], pii = sp[i0 + il];
    float bd[KK]; int bj[KK];
#pragma unroll
    for (int q = 0; q < KK; q++) { bd[q] = 3.4e38f; bj[q] = 0; }
    int j0 = half * 512;
#pragma unroll 4
    for (int jj = 0; jj < 512; jj++) {
        int j = j0 + jj;
        float de = ei - se[j];
        float dp = wrap_dphi(pii - sp[j]);
        float d = de * de + dp * dp;
        if (d < bd[KK - 1]) {
            float cd = d; int cj = j;
#pragma unroll
            for (int q = 0; q < KK; q++) {
                if (cd < bd[q]) {
                    float td = bd[q]; bd[q] = cd; cd = td;
                    int   tj = bj[q]; bj[q] = cj; cj = tj;
                }
            }
        }
    }
#pragma unroll
    for (int q = 0; q < KK; q++) { md[t * 16 + q] = bd[q]; mj[t * 16 + q] = bj[q]; }
    __syncthreads();
    if (t < 128) {
        int pa = 0, pb = 0;
        int baseA = t * 16, baseB = (t + 128) * 16;
        int obase = (b * NN + i0 + t) * KK;
#pragma unroll
        for (int q = 0; q < KK; q++) {
            float dA = md[baseA + pa], dB = md[baseB + pb];
            if (dB < dA) { g_idx[obase + q] = mj[baseB + pb]; pb++; }
            else         { g_idx[obase + q] = mj[baseA + pa]; pa++; }
        }
    }
}

// ---------------- k3: node features -> u, v (128 nodes/block, 8x8 tiles) ----------------
__global__ void __launch_bounds__(256, 2)
k3_nodeuv(const float* __restrict__ fts,
          const float* __restrict__ bn1_s, const float* __restrict__ bn1_b,
          const float* __restrict__ w_node,
          const float* __restrict__ bn2_s, const float* __restrict__ bn2_b,
          const float* __restrict__ w_e1) {
    extern __shared__ float sm3[];
    float* ra_s = sm3;               // [64 k][132]
    float* rb_s = ra_s + 64 * 132;   // [64 k][132]
    float* w_s  = rb_s + 64 * 132;   // [64 k][132] k-major; phase1 overlay below
    float* a_s  = w_s;               // [32 c][128 n]  (4096)
    float* wn_s = w_s + 4096;        // [64 o][32 c]   (2048)

    int t   = threadIdx.x;
    int gn0 = blockIdx.x * 128;
    int b   = gn0 >> 10;
    int n0  = gn0 & (NN - 1);

    for (int q = t; q < 4096; q += 256) {
        int c = q >> 7, n = q & 127;
        float v = fts[(b * 32 + c) * NN + n0 + n];
        a_s[q] = fmaxf(v * __ldg(bn1_s + c) + __ldg(bn1_b + c), 0.f);
    }
    for (int q = t; q < 2048; q += 256) wn_s[q] = w_node[q];
    __syncthreads();

    {   // nv: [64 o]x[128 n], K=32 ; tile 8o x 4n per thread
        int og = t >> 5, ngq = t & 31;
        float acc2[8][4];
#pragma unroll
        for (int i = 0; i < 8; i++)
#pragma unroll
            for (int j = 0; j < 4; j++) acc2[i][j] = 0.f;
#pragma unroll 8
        for (int k = 0; k < 32; k++) {
            float4 a4 = *(const float4*)(a_s + k * 128 + ngq * 4);
            float av[4] = {a4.x, a4.y, a4.z, a4.w};
#pragma unroll
            for (int oo = 0; oo < 8; oo++) {
                float w = wn_s[(og * 8 + oo) * 32 + k];   // broadcast within warp
                acc2[oo][0] += w * av[0]; acc2[oo][1] += w * av[1];
                acc2[oo][2] += w * av[2]; acc2[oo][3] += w * av[3];
            }
        }
#pragma unroll
        for (int oo = 0; oo < 8; oo++) {
            int o = og * 8 + oo;
            float sA = __ldg(bn2_s + o),      bA = __ldg(bn2_b + o);
            float sB = __ldg(bn2_s + 64 + o), bB = __ldg(bn2_b + 64 + o);
#pragma unroll
            for (int j = 0; j < 4; j++) {
                float nv = acc2[oo][j];
                ra_s[o * 132 + ngq * 4 + j] = fmaxf(nv * sA + bA, 0.f);
                rb_s[o * 132 + ngq * 4 + j] = fmaxf(nv * sB + bB, 0.f);
            }
        }
    }
    __syncthreads();

    int cg = t >> 4, ng = t & 15;  // 16 ch-groups x 16 node-groups, 8x8
    float acc[8][8];

#pragma unroll
    for (int pass = 0; pass < 2; pass++) {
        const float* rs = pass ? rb_s : ra_s;
        float* gout = pass ? g_v : g_u;
        // stage w_e1 cols [pass*64, pass*64+64) k-major
        for (int q = t; q < 2048; q += 256) {
            int ch = q >> 4, k4 = (q & 15) << 2;
            float4 w4 = *(const float4*)(w_e1 + ch * 132 + pass * 64 + k4);
            w_s[(k4 + 0) * 132 + ch] = w4.x;
            w_s[(k4 + 1) * 132 + ch] = w4.y;
            w_s[(k4 + 2) * 132 + ch] = w4.z;
            w_s[(k4 + 3) * 132 + ch] = w4.w;
        }
        __syncthreads();
#pragma unroll
        for (int i = 0; i < 8; i++)
#pragma unroll
            for (int j = 0; j < 8; j++) acc[i][j] = 0.f;
#pragma unroll 4
        for (int k = 0; k < 64; k++) {
            float4 wa = *(const float4*)(w_s + k * 132 + cg * 8);
            float4 wb = *(const float4*)(w_s + k * 132 + cg * 8 + 4);
            float4 rA = *(const float4*)(rs  + k * 132 + ng * 8);
            float4 rB = *(const float4*)(rs  + k * 132 + ng * 8 + 4);
            float wv[8] = {wa.x, wa.y, wa.z, wa.w, wb.x, wb.y, wb.z, wb.w};
            float rv[8] = {rA.x, rA.y, rA.z, rA.w, rB.x, rB.y, rB.z, rB.w};
#pragma unroll
            for (int i = 0; i < 8; i++)
#pragma unroll
                for (int j = 0; j < 8; j++) acc[i][j] += wv[i] * rv[j];
        }
#pragma unroll
        for (int j = 0; j < 8; j++) {
            float* op = gout + (gn0 + ng * 8 + j) * MSGD + cg * 8;
            *(float4*)op       = make_float4(acc[0][j], acc[1][j], acc[2][j], acc[3][j]);
            *(float4*)(op + 4) = make_float4(acc[4][j], acc[5][j], acc[6][j], acc[7][j]);
        }
        __syncthreads();
    }
}

// ---------------- k4: fused edge kernel -> R + block-partial pool ----------------
__global__ void k4_edge(const float* __restrict__ w_e1,
                        const float* __restrict__ bn2_s, const float* __restrict__ bn2_b,
                        const float* __restrict__ bn3_s, const float* __restrict__ bn3_b) {
    __shared__ int   js[256];
    __shared__ float rlv[256 * 4];
    __shared__ float vld[256];
    __shared__ float wc4[128 * 5];
    __shared__ float s3s[128], b3s[128];
    __shared__ float s2l[4], b2l[4];
    __shared__ float R_s[16 * 132];
    __shared__ float cpart[16];
    int t  = threadIdx.x;
    int b  = blockIdx.x >> 6;
    int blk = blockIdx.x & 63;
    int i0 = blk * 16;

    js[t] = g_idx[(b * NN + i0) * KK + t];
    if (t < 128) {
#pragma unroll
        for (int f = 0; f < 4; f++) wc4[t * 5 + f] = w_e1[t * 132 + 128 + f];
        s3s[t] = bn3_s[t]; b3s[t] = bn3_b[t];
    }
    if (t < 4) { s2l[t] = bn2_s[128 + t]; b2l[t] = bn2_b[128 + t]; }
    __syncthreads();

    {   // per-edge lv features
        int e = t;
        int i = i0 + (e >> 4), j = js[e];
        const float4* Li = (const float4*)(g_lvpack + (b * NN + i) * 8);
        const float4* Lj = (const float4*)(g_lvpack + (b * NN + j) * 8);
        float4 A0 = Li[0], A1 = Li[1], B0 = Lj[0], B1 = Lj[1];
        float pti = A1.x, ptj = B1.x;
        float ptmin = fminf(pti, ptj);
        float dphi = wrap_dphi(A1.z - B1.z);
        float drap  = A1.y - B1.y;
        float delta = sqrtf(drap * drap + dphi * dphi);
        float lndelta = logf(fmaxf(delta, EPS_F));
        float lnkt    = logf(fmaxf(ptmin * delta, EPS_F));
        float lnz     = logf(fmaxf(ptmin / fmaxf(pti + ptj, EPS_F), EPS_F));
        float sx = A0.x + B0.x, sy = A0.y + B0.y, sz = A0.z + B0.z, s4 = A0.w + B0.w;
        float lnm2 = logf(fmaxf(s4 * s4 - (sx * sx + sy * sy + sz * sz), EPS_F));
        float lv[4] = {lnkt, lnz, lndelta, lnm2};
#pragma unroll
        for (int f = 0; f < 4; f++)
            rlv[e * 4 + f] = fmaxf(lv[f] * s2l[f] + b2l[f], 0.f);
        vld[e] = A1.w * B1.w;
    }
    __syncthreads();

    if (t < 16) {
        float c = 0.f;
#pragma unroll
        for (int k = 0; k < KK; k++) c += vld[t * 16 + k];
        g_cnt[b * NN + i0 + t] = c;
        cpart[t] = c;
    }

    int nl = t >> 4, c8 = (t & 15) << 3;
    int gi = b * NN + i0 + nl;
    float4 u0 = *(const float4*)(g_u + gi * MSGD + c8);
    float4 u1 = *(const float4*)(g_u + gi * MSGD + c8 + 4);
    float ur[8] = {u0.x, u0.y, u0.z, u0.w, u1.x, u1.y, u1.z, u1.w};
    float wcr[8][4], s3r[8], b3r[8];
#pragma unroll
    for (int q = 0; q < 8; q++) {
        s3r[q] = s3s[c8 + q]; b3r[q] = b3s[c8 + q];
#pragma unroll
        for (int f = 0; f < 4; f++) wcr[q][f] = wc4[(c8 + q) * 5 + f];
    }
    float acc[8] = {0.f, 0.f, 0.f, 0.f, 0.f, 0.f, 0.f, 0.f};
#pragma unroll
    for (int k = 0; k < KK; k++) {
        int e = (nl << 4) | k;
        int j = js[e];
        const float* vp = g_v + (b * NN + j) * MSGD + c8;
        float4 v0 = *(const float4*)vp;
        float4 v1 = *(const float4*)(vp + 4);
        float vr[8] = {v0.x, v0.y, v0.z, v0.w, v1.x, v1.y, v1.z, v1.w};
        float l0 = rlv[e * 4], l1 = rlv[e * 4 + 1], l2 = rlv[e * 4 + 2], l3 = rlv[e * 4 + 3];
        float val = vld[e];
#pragma unroll
        for (int q = 0; q < 8; q++) {
            float h = ur[q] + vr[q] + wcr[q][0] * l0 + wcr[q][1] * l1
                    + wcr[q][2] * l2 + wcr[q][3] * l3;
            acc[q] += fmaxf(h * s3r[q] + b3r[q], 0.f) * val;
        }
    }
    *(float4*)(g_R + gi * MSGD + c8)     = make_float4(acc[0], acc[1], acc[2], acc[3]);
    *(float4*)(g_R + gi * MSGD + c8 + 4) = make_float4(acc[4], acc[5], acc[6], acc[7]);
#pragma unroll
    for (int q = 0; q < 8; q++) R_s[nl * 132 + c8 + q] = acc[q];
    __syncthreads();

    // block partial pool: sum over the 16 nodes
    if (t < 128) {
        float s = 0.f;
#pragma unroll
        for (int n = 0; n < 16; n++) s += R_s[n * 132 + t];
        g_Pp[(b * 64 + blk) * MSGD + t] = s;
    }
    if (t == 0) {
        float s = 0.f;
#pragma unroll
        for (int n = 0; n < 16; n++) s += cpart[n];
        g_nbp[b * 64 + blk] = s;
    }
}

// ---------------- k6: SE gate (pool = w_e2 @ P / n) ----------------
__global__ void k6_se(const float* __restrict__ w_e2,
                      const float* __restrict__ w1, const float* __restrict__ w2) {
    __shared__ float pooled[128], spool[128], tv[8];
    __shared__ float nd_s;
    int b = blockIdx.x, t = threadIdx.x;
    float s = 0.f;
#pragma unroll 8
    for (int blk = 0; blk < 64; blk++) s += g_Pp[(b * 64 + blk) * MSGD + t];
    pooled[t] = s;
    if (t == 0) {
        float n = 0.f;
#pragma unroll 8
        for (int blk = 0; blk < 64; blk++) n += g_nbp[b * 64 + blk];
        nd_s = (n == 0.f) ? 1.f : n;
    }
    __syncthreads();
    float nd = nd_s;
    const float* wr = w_e2 + t * 128;
    float d = 0.f;
#pragma unroll 4
    for (int c = 0; c < 128; c++) d += wr[c] * pooled[c];
    spool[t] = d / nd;
    __syncthreads();
    if (t < 8) {
        float z = 0.f;
        for (int c = 0; c < 128; c++) z += w1[t * 128 + c] * spool[c];
        tv[t] = fmaxf(z, 0.f);
    }
    __syncthreads();
    float z = 0.f;
#pragma unroll
    for (int o = 0; o < 8; o++) z += tv[o] * w2[t * 8 + o];
    g_y[b * 128 + t] = 1.f / (1.f + expf(-z));
}

// ---------------- k5: out = diag(y) * w_e2 @ R^T * diag(1/cnt) ----------------
__global__ void k5_out(const float* __restrict__ w_e2, float* __restrict__ outp) {
    extern __shared__ float sm5[];
    float* w_s = sm5;             // [64][132] k-major
    float* r_s = sm5 + 64 * 132;  // [64][132]
    int t   = threadIdx.x;
    int gn0 = blockIdx.x * 128;
    int b   = gn0 >> 10;
    int nn0 = gn0 & (NN - 1);
    int cg = t >> 4, ng = t & 15;
    float acc[8][8];
#pragma unroll
    for (int i = 0; i < 8; i++)
#pragma unroll
        for (int j = 0; j < 8; j++) acc[i][j] = 0.f;

    for (int k0 = 0; k0 < 128; k0 += 64) {
        for (int q = t; q < 2048; q += 256) {
            int co = q >> 4, k4 = (q & 15) << 2;
            float4 w4 = *(const float4*)(w_e2 + co * 128 + k0 + k4);
            w_s[(k4 + 0) * 132 + co] = w4.x;
            w_s[(k4 + 1) * 132 + co] = w4.y;
            w_s[(k4 + 2) * 132 + co] = w4.z;
            w_s[(k4 + 3) * 132 + co] = w4.w;
        }
        for (int q = t; q < 2048; q += 256) {
            int n = q >> 4, k4 = (q & 15) << 2;
            float4 r4 = *(const float4*)(g_R + (gn0 + n) * MSGD + k0 + k4);
            r_s[(k4 + 0) * 132 + n] = r4.x;
            r_s[(k4 + 1) * 132 + n] = r4.y;
            r_s[(k4 + 2) * 132 + n] = r4.z;
            r_s[(k4 + 3) * 132 + n] = r4.w;
        }
        __syncthreads();
#pragma unroll 4
        for (int k = 0; k < 64; k++) {
            float4 wa = *(const float4*)(w_s + k * 132 + cg * 8);
            float4 wb = *(const float4*)(w_s + k * 132 + cg * 8 + 4);
            float4 rA = *(const float4*)(r_s + k * 132 + ng * 8);
            float4 rB = *(const float4*)(r_s + k * 132 + ng * 8 + 4);
            float wv[8] = {wa.x, wa.y, wa.z, wa.w, wb.x, wb.y, wb.z, wb.w};
            float rv[8] = {rA.x, rA.y, rA.z, rA.w, rB.x, rB.y, rB.z, rB.w};
#pragma unroll
            for (int i = 0; i < 8; i++)
#pragma unroll
                for (int j = 0; j < 8; j++) acc[i][j] += wv[i] * rv[j];
        }
        __syncthreads();
    }

    float yv[8], rcv[8];
#pragma unroll
    for (int i = 0; i < 8; i++) yv[i] = g_y[b * 128 + cg * 8 + i];
#pragma unroll
    for (int j = 0; j < 8; j++)
        rcv[j] = 1.f / fmaxf(g_cnt[b * NN + nn0 + ng * 8 + j], 1.f);
#pragma unroll
    for (int i = 0; i < 8; i++) {
        float sc = yv[i];
        float* op = outp + (b * 128 + cg * 8 + i) * NN + nn0 + ng * 8;
        *(float4*)op = make_float4(acc[i][0] * sc * rcv[0], acc[i][1] * sc * rcv[1],
                                   acc[i][2] * sc * rcv[2], acc[i][3] * sc * rcv[3]);
        *(float4*)(op + 4) = make_float4(acc[i][4] * sc * rcv[4], acc[i][5] * sc * rcv[5],
                                         acc[i][6] * sc * rcv[6], acc[i][7] * sc * rcv[7]);
    }
}

extern "C" void kernel_launch(void* const* d_in, const int* in_sizes, int n_in,
                              void* d_out, int out_size) {
    const float* pts   = (const float*)d_in[0];
    const float* fts   = (const float*)d_in[1];
    const float* lvs   = (const float*)d_in[2];
    const void*  mask  = d_in[3];
    const float* bn1_s = (const float*)d_in[4];
    const float* bn1_b = (const float*)d_in[5];
    const float* w_node= (const float*)d_in[6];
    const float* bn2_s = (const float*)d_in[7];
    const float* bn2_b = (const float*)d_in[8];
    const float* w_e1  = (const float*)d_in[9];
    const float* bn3_s = (const float*)d_in[10];
    const float* bn3_b = (const float*)d_in[11];
    const float* w_e2  = (const float*)d_in[12];
    const float* se_w1 = (const float*)d_in[13];
    const float* se_w2 = (const float*)d_in[14];
    float* outp = (float*)d_out;

    cudaFuncSetAttribute(k3_nodeuv, cudaFuncAttributeMaxDynamicSharedMemorySize, 101376);
    cudaFuncSetAttribute(k5_out,    cudaFuncAttributeMaxDynamicSharedMemorySize, 67584);

    k0_detect<<<1, 32>>>((const unsigned int*)mask);
    k1_prep<<<64, 256>>>(lvs, mask);
    k2_knn<<<128, 256>>>(pts);
    k3_nodeuv<<<128, 256, 101376>>>(fts, bn1_s, bn1_b, w_node, bn2_s, bn2_b, w_e1);
    k4_edge<<<1024, 256>>>(w_e1, bn2_s, bn2_b, bn3_s, bn3_b);
    k6_se<<<16, 128>>>(w_e2, se_w1, se_w2);
    k5_out<<<128, 256, 67584>>>(w_e2, outp);
}

// round 4
// speedup vs baseline: 2.8065x; 1.5019x over previous
#include <cuda_runtime.h>
#include <math.h>
#include <float.h>

#define BB 16
#define NN 1024
#define KK 16
#define MSGD 128
#define PI_F 3.14159265358979323846f
#define TWOPI_F 6.28318530717958647692f
#define INV_TWOPI_F 0.15915494309189533577f
#define EPS_F 1e-8f

// ---------------- device scratch ----------------
__device__ int   g_maskmode;
__device__ __align__(16) float g_lvpack[BB*NN*8];   // px,py,pz,e,pt,rap,phi,mask
__device__ int   g_idx[BB*NN*KK];
__device__ __align__(16) float g_u[BB*NN*MSGD];
__device__ __align__(16) float g_v[BB*NN*MSGD];
__device__ __align__(16) float g_R[BB*NN*MSGD];
__device__ __align__(16) float g_cnt[BB*NN];
__device__ float g_Pp[BB*64*MSGD];
__device__ float g_nbp[BB*64];
__device__ float g_y[BB*MSGD];

__device__ __forceinline__ float wrap_dphi(float x) {
    float xp = x + PI_F;
    return xp - floorf(xp * INV_TWOPI_F) * TWOPI_F - PI_F;
}

// packed f32x2 helpers
__device__ __forceinline__ unsigned long long pk2(float lo, float hi) {
    unsigned long long r;
    asm("mov.b64 %0, {%1, %2};" : "=l"(r) : "f"(lo), "f"(hi));
    return r;
}
__device__ __forceinline__ void upk2(unsigned long long v, float& lo, float& hi) {
    asm("mov.b64 {%0, %1}, %2;" : "=f"(lo), "=f"(hi) : "l"(v));
}
__device__ __forceinline__ void ffma2(unsigned long long& acc,
                                      unsigned long long a, unsigned long long b) {
    asm("fma.rn.f32x2 %0, %1, %2, %0;" : "+l"(acc) : "l"(a), "l"(b));
}

// ---------------- k0: detect mask dtype ----------------
__global__ void k0_detect(const unsigned int* mw) {
    if (threadIdx.x == 0) {
        int allf = 1, alli = 1;
        for (int q = 0; q < 64; q++) {
            unsigned int w = mw[q];
            if (!(w == 0u || w == 0x3F800000u)) allf = 0;
            if (!(w == 0u || w == 1u))          alli = 0;
        }
        g_maskmode = allf ? 0 : (alli ? 1 : 2);
    }
}

// ---------------- k1: per-node lv prep + mask ----------------
__global__ void k1_prep(const float* __restrict__ lvs, const void* __restrict__ mask) {
    int gid = blockIdx.x * blockDim.x + threadIdx.x;
    if (gid >= BB * NN) return;
    int b = gid >> 10, n = gid & (NN - 1);
    int mode = g_maskmode;
    float m;
    if (mode == 0)      m = (((const float*)mask)[gid] != 0.f) ? 1.f : 0.f;
    else if (mode == 1) m = (((const int*)mask)[gid] != 0) ? 1.f : 0.f;
    else                m = (((const unsigned char*)mask)[gid] != 0) ? 1.f : 0.f;
    const float* base = lvs + b * 4 * NN + n;
    float px = base[0], py = base[NN], pz = base[2 * NN], e = base[3 * NN];
    float pt  = sqrtf(px * px + py * py);
    float rap = 0.5f * log1pf(2.f * pz / fmaxf(e - pz, 1e-20f));
    float phi = atan2f(py, px);
    float4* o = (float4*)(g_lvpack + gid * 8);
    o[0] = make_float4(px, py, pz, e);
    o[1] = make_float4(pt, rap, phi, m);
}

// ---------------- k2: warp-per-node knn, lane-distributed top-16 ----------------
__global__ void k2_knn(const float* __restrict__ pts) {
    __shared__ float se[NN], sp[NN];
    int t = threadIdx.x;
    int b = blockIdx.x >> 5;
    int chunk = blockIdx.x & 31;          // 32 nodes per block
    for (int q = t; q < NN; q += 256) {
        se[q] = pts[b * 2 * NN + q];
        sp[q] = pts[b * 2 * NN + NN + q];
    }
    __syncthreads();
    int w = t >> 5, lane = t & 31;
#pragma unroll 1
    for (int nn = 0; nn < 4; nn++) {
        int i = chunk * 32 + w * 4 + nn;
        float ei = se[i], pii = sp[i];
        float dslot = FLT_MAX;            // lanes 0..15 hold sorted top-16
        int   jslot = 0;
        float thr = FLT_MAX;
#pragma unroll 1
        for (int j0 = 0; j0 < NN; j0 += 32) {
            int j = j0 + lane;
            float de = ei - se[j];
            float dp = wrap_dphi(pii - sp[j]);
            float d  = de * de + dp * dp;
            unsigned m = __ballot_sync(0xffffffffu, d < thr);
            while (m) {
                int src = __ffs(m) - 1; m &= m - 1;
                float dv = __shfl_sync(0xffffffffu, d, src);
                if (!(dv < thr)) continue;        // stale vs updated thr (uniform)
                int jv = j0 + src;
                float prevd = __shfl_up_sync(0xffffffffu, dslot, 1);
                int   prevj = __shfl_up_sync(0xffffffffu, jslot, 1);
                bool pg = (lane > 0) && (prevd > dv);
                if (dslot > dv) {
                    dslot = pg ? prevd : dv;
                    jslot = pg ? prevj : jv;
                }
                thr = __shfl_sync(0xffffffffu, dslot, 15);
            }
        }
        if (lane < 16) g_idx[(b * NN + i) * KK + lane] = jslot;
    }
}

// ---------------- k3: node features -> u, v (512 thr, f32x2) ----------------
__global__ void __launch_bounds__(512)
k3_nodeuv(const float* __restrict__ fts,
          const float* __restrict__ bn1_s, const float* __restrict__ bn1_b,
          const float* __restrict__ w_node,
          const float* __restrict__ bn2_s, const float* __restrict__ bn2_b,
          const float* __restrict__ w_e1) {
    extern __shared__ float sm3[];
    float* ra_s = sm3;               // [64 k][132]
    float* rb_s = ra_s + 64 * 132;   // [64 k][132]
    float* w_s  = rb_s + 64 * 132;   // [64 k][132]; phase-1 overlay:
    float* a_s  = w_s;               // [32 c][128 n]
    float* wn_s = w_s + 4096;        // [64 o][32 c]

    int t   = threadIdx.x;
    int gn0 = blockIdx.x * 128;
    int b   = gn0 >> 10;
    int n0  = gn0 & (NN - 1);

    for (int q = t; q < 4096; q += 512) {
        int c = q >> 7, n = q & 127;
        float v = fts[(b * 32 + c) * NN + n0 + n];
        a_s[q] = fmaxf(v * __ldg(bn1_s + c) + __ldg(bn1_b + c), 0.f);
    }
    for (int q = t; q < 2048; q += 512) wn_s[q] = w_node[q];
    __syncthreads();

    {   // phase 1: nv [64 o]x[128 n], K=32 ; 4o x 4n per thread
        int og = t >> 5, ngq = t & 31;
        float acc2[4][4];
#pragma unroll
        for (int i = 0; i < 4; i++)
#pragma unroll
            for (int j = 0; j < 4; j++) acc2[i][j] = 0.f;
#pragma unroll 8
        for (int k = 0; k < 32; k++) {
            float4 a4 = *(const float4*)(a_s + k * 128 + ngq * 4);
            float av[4] = {a4.x, a4.y, a4.z, a4.w};
#pragma unroll
            for (int oo = 0; oo < 4; oo++) {
                float wv = wn_s[(og * 4 + oo) * 32 + k];
                acc2[oo][0] += wv * av[0]; acc2[oo][1] += wv * av[1];
                acc2[oo][2] += wv * av[2]; acc2[oo][3] += wv * av[3];
            }
        }
#pragma unroll
        for (int oo = 0; oo < 4; oo++) {
            int o = og * 4 + oo;
            float sA = __ldg(bn2_s + o),      bA = __ldg(bn2_b + o);
            float sB = __ldg(bn2_s + 64 + o), bB = __ldg(bn2_b + 64 + o);
#pragma unroll
            for (int j = 0; j < 4; j++) {
                float nv = acc2[oo][j];
                ra_s[o * 132 + ngq * 4 + j] = fmaxf(nv * sA + bA, 0.f);
                rb_s[o * 132 + ngq * 4 + j] = fmaxf(nv * sB + bB, 0.f);
            }
        }
    }
    __syncthreads();

    int cg = t >> 5, ng = t & 31;   // 16 ch-groups(8ch) x 32 node-groups(4n)
#pragma unroll
    for (int pass = 0; pass < 2; pass++) {
        const float* rs = pass ? rb_s : ra_s;
        float* gout = pass ? g_v : g_u;
        for (int q = t; q < 2048; q += 512) {
            int ch = q >> 4, k4 = (q & 15) << 2;
            float4 w4 = *(const float4*)(w_e1 + ch * 132 + pass * 64 + k4);
            w_s[(k4 + 0) * 132 + ch] = w4.x;
            w_s[(k4 + 1) * 132 + ch] = w4.y;
            w_s[(k4 + 2) * 132 + ch] = w4.z;
            w_s[(k4 + 3) * 132 + ch] = w4.w;
        }
        __syncthreads();
        unsigned long long acc[4][4];   // [ch-pair][node]
#pragma unroll
        for (int i = 0; i < 4; i++)
#pragma unroll
            for (int j = 0; j < 4; j++) acc[i][j] = 0ull;
#pragma unroll 4
        for (int k = 0; k < 64; k++) {
            float4 wa = *(const float4*)(w_s + k * 132 + cg * 8);
            float4 wb = *(const float4*)(w_s + k * 132 + cg * 8 + 4);
            float4 r4 = *(const float4*)(rs  + k * 132 + ng * 4);
            unsigned long long wp[4] = {pk2(wa.x, wa.y), pk2(wa.z, wa.w),
                                        pk2(wb.x, wb.y), pk2(wb.z, wb.w)};
            unsigned long long rd[4] = {pk2(r4.x, r4.x), pk2(r4.y, r4.y),
                                        pk2(r4.z, r4.z), pk2(r4.w, r4.w)};
#pragma unroll
            for (int i = 0; i < 4; i++)
#pragma unroll
                for (int j = 0; j < 4; j++) ffma2(acc[i][j], wp[i], rd[j]);
        }
#pragma unroll
        for (int j = 0; j < 4; j++) {
            float v0, v1, v2, v3, v4, v5, v6, v7;
            upk2(acc[0][j], v0, v1); upk2(acc[1][j], v2, v3);
            upk2(acc[2][j], v4, v5); upk2(acc[3][j], v6, v7);
            float* op = gout + (gn0 + ng * 4 + j) * MSGD + cg * 8;
            *(float4*)op       = make_float4(v0, v1, v2, v3);
            *(float4*)(op + 4) = make_float4(v4, v5, v6, v7);
        }
        __syncthreads();
    }
}

// ---------------- k4: fused edge kernel -> R + block-partial pool ----------------
__global__ void k4_edge(const float* __restrict__ w_e1,
                        const float* __restrict__ bn2_s, const float* __restrict__ bn2_b,
                        const float* __restrict__ bn3_s, const float* __restrict__ bn3_b) {
    __shared__ int   js[256];
    __shared__ float rlv[256 * 4];
    __shared__ float vld[256];
    __shared__ float wc4[128 * 5];
    __shared__ float s3s[128], b3s[128];
    __shared__ float s2l[4], b2l[4];
    __shared__ float R_s[16 * 132];
    __shared__ float cpart[16];
    int t  = threadIdx.x;
    int b  = blockIdx.x >> 6;
    int blk = blockIdx.x & 63;
    int i0 = blk * 16;

    js[t] = g_idx[(b * NN + i0) * KK + t];
    if (t < 128) {
#pragma unroll
        for (int f = 0; f < 4; f++) wc4[t * 5 + f] = w_e1[t * 132 + 128 + f];
        s3s[t] = bn3_s[t]; b3s[t] = bn3_b[t];
    }
    if (t < 4) { s2l[t] = bn2_s[128 + t]; b2l[t] = bn2_b[128 + t]; }
    __syncthreads();

    {
        int e = t;
        int i = i0 + (e >> 4), j = js[e];
        const float4* Li = (const float4*)(g_lvpack + (b * NN + i) * 8);
        const float4* Lj = (const float4*)(g_lvpack + (b * NN + j) * 8);
        float4 A0 = Li[0], A1 = Li[1], B0 = Lj[0], B1 = Lj[1];
        float pti = A1.x, ptj = B1.x;
        float ptmin = fminf(pti, ptj);
        float dphi = wrap_dphi(A1.z - B1.z);
        float drap  = A1.y - B1.y;
        float delta = sqrtf(drap * drap + dphi * dphi);
        float lndelta = logf(fmaxf(delta, EPS_F));
        float lnkt    = logf(fmaxf(ptmin * delta, EPS_F));
        float lnz     = logf(fmaxf(ptmin / fmaxf(pti + ptj, EPS_F), EPS_F));
        float sx = A0.x + B0.x, sy = A0.y + B0.y, sz = A0.z + B0.z, s4 = A0.w + B0.w;
        float lnm2 = logf(fmaxf(s4 * s4 - (sx * sx + sy * sy + sz * sz), EPS_F));
        float lv[4] = {lnkt, lnz, lndelta, lnm2};
#pragma unroll
        for (int f = 0; f < 4; f++)
            rlv[e * 4 + f] = fmaxf(lv[f] * s2l[f] + b2l[f], 0.f);
        vld[e] = A1.w * B1.w;
    }
    __syncthreads();

    if (t < 16) {
        float c = 0.f;
#pragma unroll
        for (int k = 0; k < KK; k++) c += vld[t * 16 + k];
        g_cnt[b * NN + i0 + t] = c;
        cpart[t] = c;
    }

    int nl = t >> 4, c8 = (t & 15) << 3;
    int gi = b * NN + i0 + nl;
    float4 u0 = *(const float4*)(g_u + gi * MSGD + c8);
    float4 u1 = *(const float4*)(g_u + gi * MSGD + c8 + 4);
    float ur[8] = {u0.x, u0.y, u0.z, u0.w, u1.x, u1.y, u1.z, u1.w};
    float wcr[8][4], s3r[8], b3r[8];
#pragma unroll
    for (int q = 0; q < 8; q++) {
        s3r[q] = s3s[c8 + q]; b3r[q] = b3s[c8 + q];
#pragma unroll
        for (int f = 0; f < 4; f++) wcr[q][f] = wc4[(c8 + q) * 5 + f];
    }
    float acc[8] = {0.f, 0.f, 0.f, 0.f, 0.f, 0.f, 0.f, 0.f};
#pragma unroll
    for (int k = 0; k < KK; k++) {
        int e = (nl << 4) | k;
        int j = js[e];
        const float* vp = g_v + (b * NN + j) * MSGD + c8;
        float4 v0 = *(const float4*)vp;
        float4 v1 = *(const float4*)(vp + 4);
        float vr[8] = {v0.x, v0.y, v0.z, v0.w, v1.x, v1.y, v1.z, v1.w};
        float l0 = rlv[e * 4], l1 = rlv[e * 4 + 1], l2 = rlv[e * 4 + 2], l3 = rlv[e * 4 + 3];
        float val = vld[e];
#pragma unroll
        for (int q = 0; q < 8; q++) {
            float h = ur[q] + vr[q] + wcr[q][0] * l0 + wcr[q][1] * l1
                    + wcr[q][2] * l2 + wcr[q][3] * l3;
            acc[q] += fmaxf(h * s3r[q] + b3r[q], 0.f) * val;
        }
    }
    *(float4*)(g_R + gi * MSGD + c8)     = make_float4(acc[0], acc[1], acc[2], acc[3]);
    *(float4*)(g_R + gi * MSGD + c8 + 4) = make_float4(acc[4], acc[5], acc[6], acc[7]);
#pragma unroll
    for (int q = 0; q < 8; q++) R_s[nl * 132 + c8 + q] = acc[q];
    __syncthreads();

    if (t < 128) {
        float s = 0.f;
#pragma unroll
        for (int n = 0; n < 16; n++) s += R_s[n * 132 + t];
        g_Pp[(b * 64 + blk) * MSGD + t] = s;
    }
    if (t == 0) {
        float s = 0.f;
#pragma unroll
        for (int n = 0; n < 16; n++) s += cpart[n];
        g_nbp[b * 64 + blk] = s;
    }
}

// ---------------- k6: SE gate ----------------
__global__ void k6_se(const float* __restrict__ w_e2,
                      const float* __restrict__ w1, const float* __restrict__ w2) {
    __shared__ float pooled[128], spool[128], tv[8];
    __shared__ float nd_s;
    int b = blockIdx.x, t = threadIdx.x;
    float s = 0.f;
#pragma unroll 8
    for (int blk = 0; blk < 64; blk++) s += g_Pp[(b * 64 + blk) * MSGD + t];
    pooled[t] = s;
    if (t == 0) {
        float n = 0.f;
#pragma unroll 8
        for (int blk = 0; blk < 64; blk++) n += g_nbp[b * 64 + blk];
        nd_s = (n == 0.f) ? 1.f : n;
    }
    __syncthreads();
    float nd = nd_s;
    const float* wr = w_e2 + t * 128;
    float d = 0.f;
#pragma unroll 4
    for (int c = 0; c < 128; c++) d += wr[c] * pooled[c];
    spool[t] = d / nd;
    __syncthreads();
    if (t < 8) {
        float z = 0.f;
        for (int c = 0; c < 128; c++) z += w1[t * 128 + c] * spool[c];
        tv[t] = fmaxf(z, 0.f);
    }
    __syncthreads();
    float z = 0.f;
#pragma unroll
    for (int o = 0; o < 8; o++) z += tv[o] * w2[t * 8 + o];
    g_y[b * 128 + t] = 1.f / (1.f + expf(-z));
}

// ---------------- k5: out = diag(y) * w_e2 @ R^T * diag(1/cnt) (512 thr, f32x2) ----------------
__global__ void __launch_bounds__(512)
k5_out(const float* __restrict__ w_e2, float* __restrict__ outp) {
    extern __shared__ float sm5[];
    float* w_s = sm5;             // [64 k][132] co-major-in-row
    float* r_s = sm5 + 64 * 132;  // [64 k][132] node-major-in-row
    int t   = threadIdx.x;
    int gn0 = blockIdx.x * 128;
    int b   = gn0 >> 10;
    int nn0 = gn0 & (NN - 1);
    int cg = t >> 5, ng = t & 31;   // 16 co-groups(8co) x 32 node-groups(4n)
    unsigned long long acc[4][4];
#pragma unroll
    for (int i = 0; i < 4; i++)
#pragma unroll
        for (int j = 0; j < 4; j++) acc[i][j] = 0ull;

    for (int k0 = 0; k0 < 128; k0 += 64) {
        for (int q = t; q < 2048; q += 512) {
            int co = q >> 4, k4 = (q & 15) << 2;
            float4 w4 = *(const float4*)(w_e2 + co * 128 + k0 + k4);
            w_s[(k4 + 0) * 132 + co] = w4.x;
            w_s[(k4 + 1) * 132 + co] = w4.y;
            w_s[(k4 + 2) * 132 + co] = w4.z;
            w_s[(k4 + 3) * 132 + co] = w4.w;
        }
        for (int q = t; q < 2048; q += 512) {
            int n = q >> 4, k4 = (q & 15) << 2;
            float4 r4 = *(const float4*)(g_R + (gn0 + n) * MSGD + k0 + k4);
            r_s[(k4 + 0) * 132 + n] = r4.x;
            r_s[(k4 + 1) * 132 + n] = r4.y;
            r_s[(k4 + 2) * 132 + n] = r4.z;
            r_s[(k4 + 3) * 132 + n] = r4.w;
        }
        __syncthreads();
#pragma unroll 4
        for (int k = 0; k < 64; k++) {
            float4 wa = *(const float4*)(w_s + k * 132 + cg * 8);
            float4 wb = *(const float4*)(w_s + k * 132 + cg * 8 + 4);
            float4 r4 = *(const float4*)(r_s + k * 132 + ng * 4);
            unsigned long long wp[4] = {pk2(wa.x, wa.y), pk2(wa.z, wa.w),
                                        pk2(wb.x, wb.y), pk2(wb.z, wb.w)};
            unsigned long long rd[4] = {pk2(r4.x, r4.x), pk2(r4.y, r4.y),
                                        pk2(r4.z, r4.z), pk2(r4.w, r4.w)};
#pragma unroll
            for (int i = 0; i < 4; i++)
#pragma unroll
                for (int j = 0; j < 4; j++) ffma2(acc[i][j], wp[i], rd[j]);
        }
        __syncthreads();
    }

    float yv[8], rcv[4];
#pragma unroll
    for (int i = 0; i < 8; i++) yv[i] = g_y[b * 128 + cg * 8 + i];
#pragma unroll
    for (int j = 0; j < 4; j++)
        rcv[j] = 1.f / fmaxf(g_cnt[b * NN + nn0 + ng * 4 + j], 1.f);

    float vals[8][4];
#pragma unroll
    for (int i = 0; i < 4; i++)
#pragma unroll
        for (int j = 0; j < 4; j++) {
            float lo, hi;
            upk2(acc[i][j], lo, hi);
            vals[2 * i][j] = lo; vals[2 * i + 1][j] = hi;
        }
#pragma unroll
    for (int i = 0; i < 8; i++) {
        float sc = yv[i];
        float* op = outp + (b * 128 + cg * 8 + i) * NN + nn0 + ng * 4;
        *(float4*)op = make_float4(vals[i][0] * sc * rcv[0], vals[i][1] * sc * rcv[1],
                                   vals[i][2] * sc * rcv[2], vals[i][3] * sc * rcv[3]);
    }
}

extern "C" void kernel_launch(void* const* d_in, const int* in_sizes, int n_in,
                              void* d_out, int out_size) {
    const float* pts   = (const float*)d_in[0];
    const float* fts   = (const float*)d_in[1];
    const float* lvs   = (const float*)d_in[2];
    const void*  mask  = d_in[3];
    const float* bn1_s = (const float*)d_in[4];
    const float* bn1_b = (const float*)d_in[5];
    const float* w_node= (const float*)d_in[6];
    const float* bn2_s = (const float*)d_in[7];
    const float* bn2_b = (const float*)d_in[8];
    const float* w_e1  = (const float*)d_in[9];
    const float* bn3_s = (const float*)d_in[10];
    const float* bn3_b = (const float*)d_in[11];
    const float* w_e2  = (const float*)d_in[12];
    const float* se_w1 = (const float*)d_in[13];
    const float* se_w2 = (const float*)d_in[14];
    float* outp = (float*)d_out;

    cudaFuncSetAttribute(k3_nodeuv, cudaFuncAttributeMaxDynamicSharedMemorySize, 101376);
    cudaFuncSetAttribute(k5_out,    cudaFuncAttributeMaxDynamicSharedMemorySize, 67584);

    k0_detect<<<1, 32>>>((const unsigned int*)mask);
    k1_prep<<<64, 256>>>(lvs, mask);
    k2_knn<<<512, 256>>>(pts);
    k3_nodeuv<<<128, 512, 101376>>>(fts, bn1_s, bn1_b, w_node, bn2_s, bn2_b, w_e1);
    k4_edge<<<1024, 256>>>(w_e1, bn2_s, bn2_b, bn3_s, bn3_b);
    k6_se<<<16, 128>>>(w_e2, se_w1, se_w2);
    k5_out<<<128, 512, 67584>>>(w_e2, outp);
}